// round 2
// baseline (speedup 1.0000x reference)
#include <cuda_runtime.h>
#include <math.h>

#define NB 8
#define NN 4096
#define H  64
#define CAP 64
#define NJ 128

// Scratch (allocation-free per harness rules)
static __device__ float g_h1[NB * NN * H];      // 8 MB
static __device__ float g_h2[NB * NN * H];      // 8 MB
static __device__ int   g_nidx[NB * NN * CAP];  // 8 MB
static __device__ float g_nval[NB * NN * CAP];  // 8 MB
static __device__ int   g_cnt[NB * NN];
static __device__ float g_part[NB * 16 * H];
static __device__ float g_base1[NB * H];
static __device__ float g_scores[NB * NJ];

// ---------------------------------------------------------------------------
// K1: single pass over adj (512 MB). Per row: pooled0 = adj_row · features,
// compact nonzeros to CSR scratch, run GIN-0 MLP (2->64->64) -> h1.
// ---------------------------------------------------------------------------
__global__ void __launch_bounds__(128) k_adj(
    const float* __restrict__ adj, const float* __restrict__ feat,
    const float* __restrict__ w1, const float* __restrict__ b1,
    const float* __restrict__ w2, const float* __restrict__ b2)
{
    int row = blockIdx.x;            // 0 .. NB*NN-1
    int b   = row >> 12;
    int t   = threadIdx.x;

    const float4* arow = (const float4*)(adj + (size_t)row * NN);
    const float2* fb   = (const float2*)(feat + (size_t)b * NN * 2);

    __shared__ int   s_cnt;
    __shared__ int   s_idx[CAP];
    __shared__ float s_val[CAP];
    __shared__ float rp0[128], rp1[128];
    __shared__ float st[H];

    if (t == 0) s_cnt = 0;
    __syncthreads();

    float p0 = 0.f, p1 = 0.f;
#pragma unroll
    for (int it = 0; it < 8; ++it) {
        int c4 = t + it * 128;
        float4 v = arow[c4];
        float vv[4] = {v.x, v.y, v.z, v.w};
#pragma unroll
        for (int c = 0; c < 4; ++c) {
            if (vv[c] != 0.f) {
                int col = c4 * 4 + c;
                int pos = atomicAdd(&s_cnt, 1);
                if (pos < CAP) { s_idx[pos] = col; s_val[pos] = vv[c]; }
                float2 f = fb[col];
                p0 = fmaf(vv[c], f.x, p0);
                p1 = fmaf(vv[c], f.y, p1);
            }
        }
    }
    rp0[t] = p0; rp1[t] = p1;
    __syncthreads();                  // also publishes s_cnt / s_idx / s_val
    for (int s = 64; s > 0; s >>= 1) {
        if (t < s) { rp0[t] += rp0[t + s]; rp1[t] += rp1[t + s]; }
        __syncthreads();
    }
    float P0 = rp0[0], P1 = rp1[0];
    int cnt = min(s_cnt, CAP);
    if (t == 0) g_cnt[row] = cnt;
    if (t < cnt) {
        g_nidx[(size_t)row * CAP + t] = s_idx[t];
        g_nval[(size_t)row * CAP + t] = s_val[t];
    }
    if (t < H) {
        float a = fmaf(P0, w1[t], fmaf(P1, w1[H + t], b1[t]));
        st[t] = fmaxf(a, 0.f);
    }
    __syncthreads();
    if (t < H) {
        float acc = b2[t];
#pragma unroll 16
        for (int m = 0; m < H; ++m) acc = fmaf(st[m], w2[m * H + t], acc);
        g_h1[(size_t)row * H + t] = fmaxf(acc, 0.f);
    }
}

// ---------------------------------------------------------------------------
// K2: sparse neighbor gather over h1 (~9 nbrs x 64 floats, L2-hot) + GIN-1 MLP
// ---------------------------------------------------------------------------
__global__ void __launch_bounds__(64) k_gin1(
    const float* __restrict__ w1, const float* __restrict__ b1,
    const float* __restrict__ w2, const float* __restrict__ b2)
{
    int row = blockIdx.x;
    int b   = row >> 12;
    int t   = threadIdx.x;
    int cnt = g_cnt[row];
    const float* h1b = g_h1 + (size_t)(b << 12) * H;
    const int*   ni  = g_nidx + (size_t)row * CAP;
    const float* nv  = g_nval + (size_t)row * CAP;

    float acc = 0.f;
    for (int e = 0; e < cnt; ++e)
        acc = fmaf(nv[e], h1b[(size_t)ni[e] * H + t], acc);

    __shared__ float sp[H], st[H];
    sp[t] = acc;
    __syncthreads();
    float u = b1[t];
#pragma unroll 16
    for (int m = 0; m < H; ++m) u = fmaf(sp[m], w1[m * H + t], u);
    st[t] = fmaxf(u, 0.f);
    __syncthreads();
    float o = b2[t];
#pragma unroll 16
    for (int m = 0; m < H; ++m) o = fmaf(st[m], w2[m * H + t], o);
    g_h2[(size_t)row * H + t] = fmaxf(o, 0.f);
}

// ---------------------------------------------------------------------------
// K3: deterministic graph-pool partials: part[b][c][k] over 256-node chunks
// ---------------------------------------------------------------------------
__global__ void __launch_bounds__(256) k_pool(const float* __restrict__ gp)
{
    int blk = blockIdx.x;
    int b = blk >> 4, c = blk & 15;
    int t = threadIdx.x, g = t >> 6, k = t & 63;
    const float* gpb = gp + b * NN;
    const float* h2b = g_h2 + (size_t)(b << 12) * H;
    float acc = 0.f;
    int base = c * 256;
#pragma unroll 4
    for (int it = 0; it < 64; ++it) {
        int n = base + it * 4 + g;
        acc = fmaf(gpb[n], h2b[(size_t)n * H + k], acc);
    }
    __shared__ float sr[256];
    sr[t] = acc;
    __syncthreads();
    if (t < 64)
        g_part[(b * 16 + c) * H + k] = sr[k] + sr[64 + k] + sr[128 + k] + sr[192 + k];
}

// ---------------------------------------------------------------------------
// K4: base1[b][k] = b1 + gge·W1[64:128] + pm·W1[128:192]  (per-batch fold)
// ---------------------------------------------------------------------------
__global__ void __launch_bounds__(64) k_base(
    const float* __restrict__ w1a, const float* __restrict__ b1a,
    const float* __restrict__ pm)
{
    int b = blockIdx.x, k = threadIdx.x;
    float s = 0.f;
#pragma unroll
    for (int c = 0; c < 16; ++c) s += g_part[(b * 16 + c) * H + k];
    __shared__ float sg[H], spm[H];
    sg[k] = s; spm[k] = pm[k];
    __syncthreads();
    float u = b1a[k];
#pragma unroll 8
    for (int m = 0; m < H; ++m) u = fmaf(sg[m],  w1a[(H     + m) * H + k], u);
#pragma unroll 8
    for (int m = 0; m < H; ++m) u = fmaf(spm[m], w1a[(2 * H + m) * H + k], u);
    g_base1[b * H + k] = u;
}

// ---------------------------------------------------------------------------
// K5: actor MLP per (batch, job): tanh(192->64) tanh(64->64) -> scalar *10
// ---------------------------------------------------------------------------
__global__ void __launch_bounds__(64) k_actor(
    const int* __restrict__ cand,
    const float* __restrict__ w1a,
    const float* __restrict__ w2a, const float* __restrict__ b2a,
    const float* __restrict__ w3a, const float* __restrict__ b3a)
{
    int blk = blockIdx.x;
    int b = blk >> 7, j = blk & 127;
    int t = threadIdx.x;
    int cd = cand[b * NJ + j];
    __shared__ float je[H], sa[H], sr[H];
    je[t] = g_h2[((size_t)(b << 12) + cd) * H + t];
    __syncthreads();
    float u = g_base1[b * H + t];
#pragma unroll 8
    for (int m = 0; m < H; ++m) u = fmaf(je[m], w1a[m * H + t], u);
    sa[t] = tanhf(u);
    __syncthreads();
    float v = b2a[t];
#pragma unroll 8
    for (int m = 0; m < H; ++m) v = fmaf(sa[m], w2a[m * H + t], v);
    sr[t] = tanhf(v) * w3a[t];
    __syncthreads();
    for (int s = 32; s > 0; s >>= 1) {
        if (t < s) sr[t] += sr[t + s];
        __syncthreads();
    }
    if (t == 0) g_scores[b * NJ + j] = (sr[0] + b3a[0]) * 10.f;
}

// ---------------------------------------------------------------------------
// K6: masked softmax over jobs
// ---------------------------------------------------------------------------
__global__ void __launch_bounds__(128) k_softmax(
    const int* __restrict__ mask, float* __restrict__ out)
{
    int b = blockIdx.x, t = threadIdx.x;
    float s = mask[b * NJ + t] ? -INFINITY : g_scores[b * NJ + t];
    __shared__ float sm[128];
    sm[t] = s;
    __syncthreads();
    for (int w = 64; w > 0; w >>= 1) {
        if (t < w) sm[t] = fmaxf(sm[t], sm[t + w]);
        __syncthreads();
    }
    float mx = sm[0];
    __syncthreads();
    float e = expf(s - mx);
    sm[t] = e;
    __syncthreads();
    for (int w = 64; w > 0; w >>= 1) {
        if (t < w) sm[t] += sm[t + w];
        __syncthreads();
    }
    out[b * NJ + t] = e / sm[0];
}

extern "C" void kernel_launch(void* const* d_in, const int* in_sizes, int n_in,
                              void* d_out, int out_size)
{
    const float* feat = (const float*)d_in[0];
    const float* gp   = (const float*)d_in[1];
    const float* adj  = (const float*)d_in[2];
    const int*   cand = (const int*)  d_in[3];
    const int*   mask = (const int*)  d_in[4];
    const float* g0w1 = (const float*)d_in[5];
    const float* g0b1 = (const float*)d_in[6];
    const float* g0w2 = (const float*)d_in[7];
    const float* g0b2 = (const float*)d_in[8];
    const float* g1w1 = (const float*)d_in[9];
    const float* g1b1 = (const float*)d_in[10];
    const float* g1w2 = (const float*)d_in[11];
    const float* g1b2 = (const float*)d_in[12];
    const float* pm   = (const float*)d_in[13];
    const float* aw1  = (const float*)d_in[14];
    const float* ab1  = (const float*)d_in[15];
    const float* aw2  = (const float*)d_in[16];
    const float* ab2  = (const float*)d_in[17];
    const float* aw3  = (const float*)d_in[18];
    const float* ab3  = (const float*)d_in[19];
    float* out = (float*)d_out;

    k_adj    <<<NB * NN, 128>>>(adj, feat, g0w1, g0b1, g0w2, g0b2);
    k_gin1   <<<NB * NN, 64>>>(g1w1, g1b1, g1w2, g1b2);
    k_pool   <<<NB * 16, 256>>>(gp);
    k_base   <<<NB, 64>>>(aw1, ab1, pm);
    k_actor  <<<NB * NJ, 64>>>(cand, aw1, aw2, ab2, aw3, ab3);
    k_softmax<<<NB, 128>>>(mask, out);
}